// round 12
// baseline (speedup 1.0000x reference)
#include <cuda_runtime.h>
#include <stdint.h>

#define NB 32
#define HH 512
#define WW 512
#define WPR 16        // 512 bits = 16 uint32 words per row
#define NBLK 296      // 2 CTAs/SM * 148 SMs
#define NTILEA 512    // k1 tiles: (batch, strip, chunk)
#define OWN2 11       // rows owned per phase-B warp item
#define NW2 48        // warp items per (batch, dir)
#define RPL2 8        // rows per lane slot (4 slots * 8 = 32 >= 11 + 18 halo)
#define NITEMB (NB * 2 * NW2)   // 3072
#define NWARPS (NBLK * 8)       // 2368

__device__ uint32_t g_pmask[NB][HH][WPR];
__device__ uint32_t g_gmask[NB][HH][WPR];
__device__ uint32_t g_pe[NB][HH][WPR];
__device__ uint32_t g_pm[NB][HH][WPR];
__device__ uint32_t g_pj[NB][HH][WPR];
// phase-A per-tile partials: S_p, S_pg, pec, pmc, pjc, N_p, N_g
__device__ float g_part[NB][16][7];
// phase-B structural per warp item: gec, gmc, gjc, Ie, Im, Ij
__device__ unsigned g_str[NB][NW2][6];
// phase-B medial per warp item
__device__ unsigned g_med[NB][2][NW2];
__device__ unsigned g_doneA[NB];
__device__ unsigned g_ticket;

struct Raw { float4 c; float l, r; };

__device__ __forceinline__ Raw load_raw(const float* __restrict__ img, size_t base,
                                        int r, int x0, int lane) {
    Raw o;
    if ((unsigned)r < HH) {
        const float* rp = img + base + (size_t)r * WW;
        o.c = __ldg((const float4*)rp + (x0 >> 2));
        o.l = 0.f; o.r = 0.f;
        if (lane == 0 && x0 > 0) o.l = __ldg(rp + x0 - 1);
        if (lane == 31 && x0 + 4 < WW) o.r = __ldg(rp + x0 + 4);
    } else {
        o.c = make_float4(0.f, 0.f, 0.f, 0.f);
        o.l = 0.f; o.r = 0.f;
    }
    return o;
}

__device__ __forceinline__ float4 make_h(const Raw& a, int lane) {
    float left  = __shfl_up_sync(0xFFFFFFFFu, a.c.w, 1);
    float right = __shfl_down_sync(0xFFFFFFFFu, a.c.x, 1);
    if (lane == 0)  left = a.l;
    if (lane == 31) right = a.r;
    float4 h;
    h.x = left  + a.c.x + a.c.y;
    h.y = a.c.x + a.c.y + a.c.z;
    h.z = a.c.y + a.c.z + a.c.w;
    h.w = a.c.z + a.c.w + right;
    return h;
}

__device__ __forceinline__ uint64_t shfl64_up8(uint64_t v) {
    unsigned lo = __shfl_up_sync(0xFFFFFFFFu, (unsigned)v, 8);
    unsigned hi = __shfl_up_sync(0xFFFFFFFFu, (unsigned)(v >> 32), 8);
    return ((uint64_t)hi << 32) | lo;
}
__device__ __forceinline__ uint64_t shfl64_dn8(uint64_t v) {
    unsigned lo = __shfl_down_sync(0xFFFFFFFFu, (unsigned)v, 8);
    unsigned hi = __shfl_down_sync(0xFFFFFFFFu, (unsigned)(v >> 32), 8);
    return ((uint64_t)hi << 32) | lo;
}
__device__ __forceinline__ unsigned warp_red(unsigned v) {
#pragma unroll
    for (int off = 16; off > 0; off >>= 1)
        v += __shfl_down_sync(0xFFFFFFFFu, v, off);
    return v;
}

__shared__ float sm_red[8][7];
__shared__ float smf[32][8][15];
__shared__ bool sm_last;

// ---- phase A: pred float stencil + mask packing for one 128x128 tile ----
__device__ void do_tileA(int t, const float* __restrict__ pred,
                         const float* __restrict__ gt) {
    const int tid = threadIdx.x, lane = tid & 31, w8 = tid >> 5;
    const int b = t >> 4, s = (t >> 2) & 3, c = t & 3;
    const int x0 = s * 128 + lane * 4;
    const int r0 = c * 128 + w8 * 16;
    const size_t base = (size_t)b * (HH * WW);

    Raw prm = load_raw(pred, base, r0 - 1, x0, lane);
    Raw pr0 = load_raw(pred, base, r0,     x0, lane);
    Raw prn = load_raw(pred, base, r0 + 1, x0, lane);
    float4 php = make_h(prm, lane), phc = make_h(pr0, lane);
    float4 pcc = pr0.c;
    float4 gcur = __ldg((const float4*)(gt + base + (size_t)r0 * WW + x0));

    float Sp = 0.f, Spg = 0.f;
    unsigned pec = 0, pmc = 0, pjc = 0, cP = 0, cG = 0;

    for (int i = 0; i < 16; i++) {
        const int r = r0 + i;
        Raw pr2 = load_raw(pred, base, r + 2, x0, lane);
        float4 gnx = make_float4(0.f, 0.f, 0.f, 0.f);
        if (r + 1 < HH)
            gnx = __ldg((const float4*)(gt + base + (size_t)(r + 1) * WW + x0));
        float4 phn = make_h(prn, lane);

        const float pcv[4] = {pcc.x, pcc.y, pcc.z, pcc.w};
        const float gcv[4] = {gcur.x, gcur.y, gcur.z, gcur.w};
        const float nps[4] = {php.x + phc.x + phn.x, php.y + phc.y + phn.y,
                              php.z + phc.z + phn.z, php.w + phc.w + phn.w};

        unsigned pn = 0, gn = 0, pen = 0, pmn = 0, pjn = 0;
#pragma unroll
        for (int j = 0; j < 4; j++) {
            const float pc = pcv[j], gc = gcv[j];
            const bool pon = pc > 0.5f;
            const bool gon = gc > 0.5f;
            const float np = nps[j] - pc;
            const bool pe = pon && (np == 1.0f);
            const bool pm = pon && (np == 2.0f);
            const bool pj = pon && (np > 2.0f);
            Sp += pc;
            Spg += gon ? pc : 0.f;
            pn |= (unsigned)pon << j;
            gn |= (unsigned)gon << j;
            pen |= (unsigned)pe << j;
            pmn |= (unsigned)pm << j;
            pjn |= (unsigned)pj << j;
        }
        cP += __popc(pn); cG += __popc(gn);
        pec += __popc(pen); pmc += __popc(pmn); pjc += __popc(pjn);

        const unsigned grpmask = 0xFFu << (lane & 24);
        const unsigned sh = (lane & 7) * 4;
        unsigned pw = __reduce_or_sync(grpmask, pn << sh);
        unsigned gw = __reduce_or_sync(grpmask, gn << sh);
        unsigned ew = __reduce_or_sync(grpmask, pen << sh);
        unsigned mw = __reduce_or_sync(grpmask, pmn << sh);
        unsigned jw = __reduce_or_sync(grpmask, pjn << sh);
        if ((lane & 7) == 0) {
            const int wi = s * 4 + (lane >> 3);
            g_pmask[b][r][wi] = pw;
            g_gmask[b][r][wi] = gw;
            g_pe[b][r][wi] = ew;
            g_pm[b][r][wi] = mw;
            g_pj[b][r][wi] = jw;
        }

        php = phc; phc = phn; pcc = prn.c; prn = pr2; gcur = gnx;
    }

    float v7[7] = {Sp, Spg, (float)pec, (float)pmc, (float)pjc, (float)cP, (float)cG};
#pragma unroll
    for (int k = 0; k < 7; k++) {
        float v = v7[k];
#pragma unroll
        for (int off = 16; off > 0; off >>= 1)
            v += __shfl_down_sync(0xFFFFFFFFu, v, off);
        if (lane == 0) sm_red[w8][k] = v;
    }
    __syncthreads();
    if (w8 == 0) {
#pragma unroll
        for (int k = 0; k < 7; k++) {
            float v = (lane < 8) ? sm_red[lane][k] : 0.0f;
#pragma unroll
            for (int off = 4; off > 0; off >>= 1)
                v += __shfl_down_sync(0xFFFFFFFFu, v, off);
            if (lane == 0) g_part[b][s * 4 + c][k] = v;
        }
    }
    // publish: masks + partials of this tile are done
    __threadfence();
    __syncthreads();
    if (tid == 0) atomicAdd(&g_doneA[b], 1u);
}

// ---- phase B: one warp item = (batch, dir, 11-row span) ----
__device__ void do_itemB(int it, int lane) {
    const int b = it / 96;
    const int rem = it % 96;
    const int dir = rem / 48;
    const int Wc = rem % 48;
    const int ownstart = Wc * OWN2;

    if (ownstart >= HH) {   // empty item: publish zeros
        if (lane == 0) {
            if (dir == 0)
#pragma unroll
                for (int k = 0; k < 6; k++) g_str[b][Wc][k] = 0u;
            g_med[b][dir][Wc] = 0u;
        }
        return;
    }

    // wait until batch b's masks are complete (16 tiles)
    {
        volatile unsigned* f = &g_doneA[b];
        while (*f < 16u) __nanosleep(200);
        __threadfence();
    }

    const int ownend = (ownstart + OWN2 > HH) ? HH : ownstart + OWN2;
    const int loadstart = ownstart - 9;
    const int w = lane & 7, s = lane >> 3;

    const uint64_t* refm = (dir == 0) ? (const uint64_t*)&g_gmask[b][0][0]
                                      : (const uint64_t*)&g_pmask[b][0][0];
    const uint64_t* tgm  = (dir == 0) ? (const uint64_t*)&g_pmask[b][0][0]
                                      : (const uint64_t*)&g_gmask[b][0][0];

    uint64_t cur[RPL2], tg[RPL2];
#pragma unroll
    for (int j = 0; j < RPL2; j++) {
        int rr = loadstart + s * RPL2 + j;
        bool in = (unsigned)rr < HH;
        cur[j] = in ? refm[rr * 8 + w] : 0ull;
        bool ow = (rr >= ownstart) && (rr < ownend);
        tg[j] = ow ? tgm[rr * 8 + w] : 0ull;
    }

    // structural on gt (dir==0): bit-sliced 8-neighbor counter, exact
    if (dir == 0) {
        uint64_t cu_m1 = shfl64_up8(cur[RPL2 - 1]);
        uint64_t cu_p1 = shfl64_dn8(cur[0]);
        if (s == 0) cu_m1 = 0ull;
        if (s == 3) cu_p1 = 0ull;
        unsigned gec = 0, gmc = 0, gjc = 0, Ie = 0, Im = 0, Ij = 0;
#pragma unroll
        for (int j = 0; j < RPL2; j++) {
            int rr = loadstart + s * RPL2 + j;
            uint64_t ra = (j > 0) ? cur[j - 1] : cu_m1;
            uint64_t rb = cur[j];
            uint64_t rc = (j < RPL2 - 1) ? cur[j + 1] : cu_p1;
            uint64_t rows[3] = {ra, rb, rc};
            uint64_t fl[3], fr[3];
#pragma unroll
            for (int t = 0; t < 3; t++) {
                unsigned hb = (unsigned)(rows[t] >> 63);
                unsigned lb = (unsigned)rows[t] & 1u;
                unsigned vfl = __shfl_up_sync(0xFFFFFFFFu, hb, 1);
                unsigned vfr = __shfl_down_sync(0xFFFFFFFFu, lb, 1);
                fl[t] = (rows[t] << 1) | (w > 0 ? (uint64_t)vfl : 0ull);
                fr[t] = (rows[t] >> 1) | (w < 7 ? ((uint64_t)vfr) << 63 : 0ull);
            }
            if (rr >= ownstart && rr < ownend) {
                uint64_t in8[8] = {fl[0], ra, fr[0], fl[1], fr[1], fl[2], rc, fr[2]};
                uint64_t c0 = 0, c1 = 0, ge4 = 0;
#pragma unroll
                for (int t = 0; t < 8; t++) {
                    uint64_t car = c0 & in8[t];
                    c0 ^= in8[t];
                    uint64_t car2 = c1 & car;
                    c1 ^= car;
                    ge4 |= car2;
                }
                uint64_t g = rb;
                uint64_t geW = g & c0 & ~c1 & ~ge4;
                uint64_t gmW = g & ~c0 & c1 & ~ge4;
                uint64_t gjW = g & (ge4 | (c0 & c1));
                gec += __popcll(geW); gmc += __popcll(gmW); gjc += __popcll(gjW);
                uint64_t peW = ((const uint64_t*)&g_pe[b][0][0])[rr * 8 + w];
                uint64_t pmW = ((const uint64_t*)&g_pm[b][0][0])[rr * 8 + w];
                uint64_t pjW = ((const uint64_t*)&g_pj[b][0][0])[rr * 8 + w];
                Ie += __popcll(geW & peW);
                Im += __popcll(gmW & pmW);
                Ij += __popcll(gjW & pjW);
            }
        }
        unsigned sr[6] = {gec, gmc, gjc, Ie, Im, Ij};
#pragma unroll
        for (int t = 0; t < 6; t++) {
            unsigned v = warp_red(sr[t]);
            if (lane == 0) g_str[b][Wc][t] = v;
        }
    }

    // iterated dilation with early exit
    unsigned acc = 0;
    uint64_t hz[RPL2];
#pragma unroll 1
    for (int k = 1; k <= 9; k++) {
#pragma unroll
        for (int j = 0; j < RPL2; j++) {
            unsigned hb = (unsigned)(cur[j] >> 63);
            unsigned lb = (unsigned)cur[j] & 1u;
            unsigned vfl = __shfl_up_sync(0xFFFFFFFFu, hb, 1);
            unsigned vfr = __shfl_down_sync(0xFFFFFFFFu, lb, 1);
            hz[j] = cur[j] | (cur[j] << 1) | (cur[j] >> 1)
                  | (w > 0 ? (uint64_t)vfl : 0ull)
                  | (w < 7 ? ((uint64_t)vfr) << 63 : 0ull);
        }
        uint64_t hz_m1 = shfl64_up8(hz[RPL2 - 1]);
        uint64_t hz_p1 = shfl64_dn8(hz[0]);
        if (s == 0) hz_m1 = 0ull;
        if (s == 3) hz_p1 = 0ull;
        uint64_t un = 0;
#pragma unroll
        for (int j = 0; j < RPL2; j++) {
            uint64_t v = hz[j] | ((j > 0) ? hz[j - 1] : hz_m1)
                               | ((j < RPL2 - 1) ? hz[j + 1] : hz_p1);
            cur[j] = v;
            uint64_t u = tg[j] & ~v;
            un |= u;
            acc += (unsigned)__popcll(u);
        }
        if (!__any_sync(0xFFFFFFFFu, un != 0ull)) break;
    }
    {
        unsigned v = warp_red(acc);
        if (lane == 0) g_med[b][dir][Wc] = v;
    }
}

__global__ void __launch_bounds__(256, 2) mono(const float* __restrict__ pred,
                                               const float* __restrict__ gt,
                                               float* __restrict__ out) {
    const int bk = blockIdx.x;
    const int tid = threadIdx.x, lane = tid & 31, wid = tid >> 5;

    // phase A (block-uniform loop)
    for (int t = bk; t < NTILEA; t += NBLK)
        do_tileA(t, pred, gt);

    // phase B (warp-level items, per-batch spin)
    const int wgid = bk * 8 + wid;
    for (int it = wgid; it < NITEMB; it += NWARPS)
        do_itemB(it, lane);

    // ticket: last block folds and writes the scalar
    __syncthreads();
    __threadfence();
    if (tid == 0) {
        unsigned old = atomicAdd(&g_ticket, 1u);
        sm_last = (old == NBLK - 1);
    }
    __syncthreads();
    if (!sm_last) return;
    __threadfence();

    {
        const int fb = tid >> 3, grp = tid & 7;
        float part[15];
#pragma unroll
        for (int k = 0; k < 15; k++) part[k] = 0.f;
#pragma unroll
        for (int q = 0; q < 2; q++) {
            int sc = grp * 2 + q;
#pragma unroll
            for (int k = 0; k < 7; k++) part[k] += g_part[fb][sc][k];
        }
#pragma unroll
        for (int q = 0; q < 6; q++) {
            int Wq = grp * 6 + q;
#pragma unroll
            for (int k = 0; k < 6; k++) part[7 + k] += (float)g_str[fb][Wq][k];
            part[13] += (float)g_med[fb][0][Wq];
            part[14] += (float)g_med[fb][1][Wq];
        }
#pragma unroll
        for (int k = 0; k < 15; k++) smf[fb][grp][k] = part[k];
    }
    __syncthreads();
    if (tid < 32) {
        const int bb = tid;
        float a[15];
#pragma unroll
        for (int k = 0; k < 15; k++) {
            float v = 0.f;
#pragma unroll
            for (int g2 = 0; g2 < 8; g2++) v += smf[bb][g2][k];
            a[k] = v;
        }
        const float Sp = a[0], Spg = a[1];
        const float pec = a[2], pmc = a[3], pjc = a[4];
        const float Np = a[5], Ng = a[6];
        const float gec = a[7], gmc = a[8], gjc = a[9];
        const float Ie = a[10], Im = a[11], Ij = a[12];
        const float medP = a[13] + Np;   // + d>=1 term for every on-pixel
        const float medG = a[14] + Ng;
        const float Sg = Ng;

        float dice = (2.0f * Spg + 1.0f) / (Sp + Sg + 1.0f);
        float eiou = (Ie + 1.0f) / (pec + gec - Ie + 1.0f);
        float miou = (Im + 1.0f) / (pmc + gmc - Im + 1.0f);
        float jiou = (Ij + 1.0f) / (pjc + gjc - Ij + 1.0f);
        float total3 = gec + gjc + gmc + 1.0f;
        float sloss = 1.0f - ((gec / total3) * eiou + (gjc / total3) * jiou
                              + (gmc / total3) * miou);
        float p2g = medP / (Np + 1.0f);
        float g2p = medG / (Ng + 1.0f);
        float med = ((p2g + g2p) * 0.5f) / 10.0f;

        float sd = dice, ss = sloss, sme = med;
#pragma unroll
        for (int off = 16; off > 0; off >>= 1) {
            sd  += __shfl_down_sync(0xFFFFFFFFu, sd, off);
            ss  += __shfl_down_sync(0xFFFFFFFFu, ss, off);
            sme += __shfl_down_sync(0xFFFFFFFFu, sme, off);
        }
        // reset per-replay state
        g_doneA[tid] = 0u;
        if (tid == 0) {
            float dice_loss = 1.0f - sd / 32.0f;
            float structural_loss = ss / 32.0f;
            float medial_loss = sme / 32.0f;
            float avg = (dice_loss + structural_loss + medial_loss) / 3.0f;
            out[0] = dice_loss / (dice_loss + 1.0f) * avg
                   + structural_loss / (structural_loss + 1.0f) * avg
                   + medial_loss / (medial_loss + 1.0f) * avg;
            g_ticket = 0u;
        }
    }
}

extern "C" void kernel_launch(void* const* d_in, const int* in_sizes, int n_in,
                              void* d_out, int out_size) {
    const float* pred = (const float*)d_in[0];
    const float* gt   = (const float*)d_in[1];
    float* out = (float*)d_out;
    mono<<<NBLK, 256>>>(pred, gt, out);
}

// round 13
// speedup vs baseline: 1.3166x; 1.3166x over previous
#include <cuda_runtime.h>
#include <stdint.h>

#define NB 32
#define HH 512
#define WW 512
#define WPR 16   // 512 bits = 16 uint32 words per row
#define OWN2 11  // rows owned per k2 warp item
#define NW2 48   // warp items per (batch, dir)
#define RPL2 8   // rows per lane slot (4 slots * 8 = 32 >= 11 + 18 halo)
#define K2BLK 384   // 3072 warp items / 8 warps per block

__device__ uint32_t g_pmask[NB][HH][WPR];
__device__ uint32_t g_gmask[NB][HH][WPR];
__device__ uint32_t g_pe[NB][HH][WPR];
__device__ uint32_t g_pm[NB][HH][WPR];
__device__ uint32_t g_pj[NB][HH][WPR];
// k1 per-block partials: S_p, S_pg, pec, pmc, pjc, N_p, N_g  (32 tiles/batch)
__device__ float g_part[NB][32][7];
// k2 structural per warp item: gec, gmc, gjc, Ie, Im, Ij
__device__ unsigned g_str[NB][NW2][6];
// k2 medial per warp item
__device__ unsigned g_med[NB][2][NW2];
__device__ unsigned g_ticket = 0;

struct Raw { float4 c; float l, r; };

__device__ __forceinline__ Raw load_raw(const float* __restrict__ img, size_t base,
                                        int r, int x0, int lane) {
    Raw o;
    if ((unsigned)r < HH) {
        const float* rp = img + base + (size_t)r * WW;
        o.c = __ldg((const float4*)rp + (x0 >> 2));
        o.l = 0.f; o.r = 0.f;
        if (lane == 0 && x0 > 0) o.l = __ldg(rp + x0 - 1);
        if (lane == 31 && x0 + 4 < WW) o.r = __ldg(rp + x0 + 4);
    } else {
        o.c = make_float4(0.f, 0.f, 0.f, 0.f);
        o.l = 0.f; o.r = 0.f;
    }
    return o;
}

__device__ __forceinline__ float4 make_h(const Raw& a, int lane) {
    float left  = __shfl_up_sync(0xFFFFFFFFu, a.c.w, 1);
    float right = __shfl_down_sync(0xFFFFFFFFu, a.c.x, 1);
    if (lane == 0)  left = a.l;
    if (lane == 31) right = a.r;
    float4 h;
    h.x = left  + a.c.x + a.c.y;
    h.y = a.c.x + a.c.y + a.c.z;
    h.z = a.c.y + a.c.z + a.c.w;
    h.w = a.c.z + a.c.w + right;
    return h;
}

// 1024 blocks = (batch, x-strip 0..3, row-chunk 0..7), 256 threads = 8 warps,
// warp owns 8 rows. Pred float stencil + mask packing; gt math lives in k2.
__global__ void __launch_bounds__(256) k1_pixel(const float* __restrict__ pred,
                                                const float* __restrict__ gt) {
    const int tid = threadIdx.x, lane = tid & 31, w8 = tid >> 5;
    const int blk = blockIdx.x;
    const int b = blk >> 5, s = (blk >> 3) & 3, c = blk & 7;
    const int x0 = s * 128 + lane * 4;
    const int r0 = c * 64 + w8 * 8;
    const size_t base = (size_t)b * (HH * WW);

    Raw prm = load_raw(pred, base, r0 - 1, x0, lane);
    Raw pr0 = load_raw(pred, base, r0,     x0, lane);
    Raw prn = load_raw(pred, base, r0 + 1, x0, lane);
    float4 php = make_h(prm, lane), phc = make_h(pr0, lane);
    float4 pcc = pr0.c;
    float4 gcur = __ldg((const float4*)(gt + base + (size_t)r0 * WW + x0));

    float Sp = 0.f, Spg = 0.f;
    unsigned pec = 0, pmc = 0, pjc = 0, cP = 0, cG = 0;

    for (int i = 0; i < 8; i++) {
        const int r = r0 + i;
        Raw pr2 = load_raw(pred, base, r + 2, x0, lane);
        float4 gnx = make_float4(0.f, 0.f, 0.f, 0.f);
        if (r + 1 < HH)
            gnx = __ldg((const float4*)(gt + base + (size_t)(r + 1) * WW + x0));
        float4 phn = make_h(prn, lane);

        const float pcv[4] = {pcc.x, pcc.y, pcc.z, pcc.w};
        const float gcv[4] = {gcur.x, gcur.y, gcur.z, gcur.w};
        const float nps[4] = {php.x + phc.x + phn.x, php.y + phc.y + phn.y,
                              php.z + phc.z + phn.z, php.w + phc.w + phn.w};

        unsigned pn = 0, gn = 0, pen = 0, pmn = 0, pjn = 0;
#pragma unroll
        for (int j = 0; j < 4; j++) {
            const float pc = pcv[j], gc = gcv[j];
            const bool pon = pc > 0.5f;
            const bool gon = gc > 0.5f;
            const float np = nps[j] - pc;
            const bool pe = pon && (np == 1.0f);
            const bool pm = pon && (np == 2.0f);
            const bool pj = pon && (np > 2.0f);
            Sp += pc;
            Spg += gon ? pc : 0.f;
            pn |= (unsigned)pon << j;
            gn |= (unsigned)gon << j;
            pen |= (unsigned)pe << j;
            pmn |= (unsigned)pm << j;
            pjn |= (unsigned)pj << j;
        }
        cP += __popc(pn); cG += __popc(gn);
        pec += __popc(pen); pmc += __popc(pmn); pjc += __popc(pjn);

        const unsigned grpmask = 0xFFu << (lane & 24);
        const unsigned sh = (lane & 7) * 4;
        unsigned pw = __reduce_or_sync(grpmask, pn << sh);
        unsigned gw = __reduce_or_sync(grpmask, gn << sh);
        unsigned ew = __reduce_or_sync(grpmask, pen << sh);
        unsigned mw = __reduce_or_sync(grpmask, pmn << sh);
        unsigned jw = __reduce_or_sync(grpmask, pjn << sh);
        if ((lane & 7) == 0) {
            const int wi = s * 4 + (lane >> 3);
            g_pmask[b][r][wi] = pw;
            g_gmask[b][r][wi] = gw;
            g_pe[b][r][wi] = ew;
            g_pm[b][r][wi] = mw;
            g_pj[b][r][wi] = jw;
        }

        php = phc; phc = phn; pcc = prn.c; prn = pr2; gcur = gnx;
    }

    // block reduce 7 values -> unique g_part slot
    float v7[7] = {Sp, Spg, (float)pec, (float)pmc, (float)pjc, (float)cP, (float)cG};
    __shared__ float sm_red[8][7];
#pragma unroll
    for (int k = 0; k < 7; k++) {
        float v = v7[k];
#pragma unroll
        for (int off = 16; off > 0; off >>= 1)
            v += __shfl_down_sync(0xFFFFFFFFu, v, off);
        if (lane == 0) sm_red[w8][k] = v;
    }
    __syncthreads();
    if (w8 == 0) {
#pragma unroll
        for (int k = 0; k < 7; k++) {
            float v = (lane < 8) ? sm_red[lane][k] : 0.0f;
#pragma unroll
            for (int off = 4; off > 0; off >>= 1)
                v += __shfl_down_sync(0xFFFFFFFFu, v, off);
            if (lane == 0) g_part[b][s * 8 + c][k] = v;
        }
    }
}

__device__ __forceinline__ uint64_t shfl64_up8(uint64_t v) {
    unsigned lo = __shfl_up_sync(0xFFFFFFFFu, (unsigned)v, 8);
    unsigned hi = __shfl_up_sync(0xFFFFFFFFu, (unsigned)(v >> 32), 8);
    return ((uint64_t)hi << 32) | lo;
}
__device__ __forceinline__ uint64_t shfl64_dn8(uint64_t v) {
    unsigned lo = __shfl_down_sync(0xFFFFFFFFu, (unsigned)v, 8);
    unsigned hi = __shfl_down_sync(0xFFFFFFFFu, (unsigned)(v >> 32), 8);
    return ((uint64_t)hi << 32) | lo;
}
__device__ __forceinline__ unsigned warp_red(unsigned v) {
#pragma unroll
    for (int off = 16; off > 0; off >>= 1)
        v += __shfl_down_sync(0xFFFFFFFFu, v, off);
    return v;
}

// 384 blocks, 8 warps each; exactly ONE warp item per warp:
// item = (batch, dir, 11-row span). Warp loads 29 effective rows (9-row halos)
// into registers, dilates via shuffles with early exit; dir=0 items also do
// gt structural classes (bit CSA) + intersections. Last block folds all.
__global__ void __launch_bounds__(256) k2_dilate(float* __restrict__ out) {
    const int tid = threadIdx.x, lane = tid & 31, wid = tid >> 5;
    const int it = blockIdx.x * 8 + wid;
    const int b = it / 96;
    const int rem = it % 96;
    const int dir = rem / 48;
    const int Wc = rem % 48;
    const int ownstart = Wc * OWN2;
    const int w = lane & 7, s = lane >> 3;

    if (ownstart < HH) {
        const int ownend = (ownstart + OWN2 > HH) ? HH : ownstart + OWN2;
        const int loadstart = ownstart - 9;

        const uint64_t* refm = (dir == 0) ? (const uint64_t*)&g_gmask[b][0][0]
                                          : (const uint64_t*)&g_pmask[b][0][0];
        const uint64_t* tgm  = (dir == 0) ? (const uint64_t*)&g_pmask[b][0][0]
                                          : (const uint64_t*)&g_gmask[b][0][0];

        uint64_t cur[RPL2], tg[RPL2];
#pragma unroll
        for (int j = 0; j < RPL2; j++) {
            int rr = loadstart + s * RPL2 + j;
            bool in = (unsigned)rr < HH;
            cur[j] = in ? refm[rr * 8 + w] : 0ull;
            bool ow = (rr >= ownstart) && (rr < ownend);
            tg[j] = ow ? tgm[rr * 8 + w] : 0ull;
        }

        // structural on gt (dir==0): bit-sliced 8-neighbor counter, exact
        if (dir == 0) {
            uint64_t cu_m1 = shfl64_up8(cur[RPL2 - 1]);
            uint64_t cu_p1 = shfl64_dn8(cur[0]);
            if (s == 0) cu_m1 = 0ull;
            if (s == 3) cu_p1 = 0ull;
            unsigned gec = 0, gmc = 0, gjc = 0, Ie = 0, Im = 0, Ij = 0;
#pragma unroll
            for (int j = 0; j < RPL2; j++) {
                int rr = loadstart + s * RPL2 + j;
                uint64_t ra = (j > 0) ? cur[j - 1] : cu_m1;
                uint64_t rb = cur[j];
                uint64_t rc = (j < RPL2 - 1) ? cur[j + 1] : cu_p1;
                uint64_t rows[3] = {ra, rb, rc};
                uint64_t fl[3], fr[3];
#pragma unroll
                for (int t = 0; t < 3; t++) {
                    unsigned hb = (unsigned)(rows[t] >> 63);
                    unsigned lb = (unsigned)rows[t] & 1u;
                    unsigned vfl = __shfl_up_sync(0xFFFFFFFFu, hb, 1);
                    unsigned vfr = __shfl_down_sync(0xFFFFFFFFu, lb, 1);
                    fl[t] = (rows[t] << 1) | (w > 0 ? (uint64_t)vfl : 0ull);
                    fr[t] = (rows[t] >> 1) | (w < 7 ? ((uint64_t)vfr) << 63 : 0ull);
                }
                if (rr >= ownstart && rr < ownend) {
                    uint64_t in8[8] = {fl[0], ra, fr[0], fl[1], fr[1], fl[2], rc, fr[2]};
                    uint64_t c0 = 0, c1 = 0, ge4 = 0;
#pragma unroll
                    for (int t = 0; t < 8; t++) {
                        uint64_t car = c0 & in8[t];
                        c0 ^= in8[t];
                        uint64_t car2 = c1 & car;
                        c1 ^= car;
                        ge4 |= car2;
                    }
                    uint64_t g = rb;
                    uint64_t geW = g & c0 & ~c1 & ~ge4;
                    uint64_t gmW = g & ~c0 & c1 & ~ge4;
                    uint64_t gjW = g & (ge4 | (c0 & c1));
                    gec += __popcll(geW); gmc += __popcll(gmW); gjc += __popcll(gjW);
                    uint64_t peW = ((const uint64_t*)&g_pe[b][0][0])[rr * 8 + w];
                    uint64_t pmW = ((const uint64_t*)&g_pm[b][0][0])[rr * 8 + w];
                    uint64_t pjW = ((const uint64_t*)&g_pj[b][0][0])[rr * 8 + w];
                    Ie += __popcll(geW & peW);
                    Im += __popcll(gmW & pmW);
                    Ij += __popcll(gjW & pjW);
                }
            }
            unsigned sr[6] = {gec, gmc, gjc, Ie, Im, Ij};
#pragma unroll
            for (int t = 0; t < 6; t++) {
                unsigned v = warp_red(sr[t]);
                if (lane == 0) g_str[b][Wc][t] = v;
            }
        }

        // iterated dilation with early exit
        unsigned acc = 0;
        uint64_t hz[RPL2];
#pragma unroll 1
        for (int k = 1; k <= 9; k++) {
#pragma unroll
            for (int j = 0; j < RPL2; j++) {
                unsigned hb = (unsigned)(cur[j] >> 63);
                unsigned lb = (unsigned)cur[j] & 1u;
                unsigned vfl = __shfl_up_sync(0xFFFFFFFFu, hb, 1);
                unsigned vfr = __shfl_down_sync(0xFFFFFFFFu, lb, 1);
                hz[j] = cur[j] | (cur[j] << 1) | (cur[j] >> 1)
                      | (w > 0 ? (uint64_t)vfl : 0ull)
                      | (w < 7 ? ((uint64_t)vfr) << 63 : 0ull);
            }
            uint64_t hz_m1 = shfl64_up8(hz[RPL2 - 1]);
            uint64_t hz_p1 = shfl64_dn8(hz[0]);
            if (s == 0) hz_m1 = 0ull;
            if (s == 3) hz_p1 = 0ull;
            uint64_t un = 0;
#pragma unroll
            for (int j = 0; j < RPL2; j++) {
                uint64_t v = hz[j] | ((j > 0) ? hz[j - 1] : hz_m1)
                                   | ((j < RPL2 - 1) ? hz[j + 1] : hz_p1);
                cur[j] = v;
                uint64_t u = tg[j] & ~v;
                un |= u;
                acc += (unsigned)__popcll(u);
            }
            if (!__any_sync(0xFFFFFFFFu, un != 0ull)) break;
        }
        unsigned v = warp_red(acc);
        if (lane == 0) g_med[b][dir][Wc] = v;
    } else {
        // empty item (Wc*11 >= 512): publish zeros
        if (lane == 0) {
            if (dir == 0)
#pragma unroll
                for (int k = 0; k < 6; k++) g_str[b][Wc][k] = 0u;
            g_med[b][dir][Wc] = 0u;
        }
    }

    // ---- ticket: last block computes the final scalar ----
    __shared__ bool isLast;
    __threadfence();
    __syncthreads();
    if (tid == 0) {
        unsigned old = atomicAdd(&g_ticket, 1u);
        isLast = (old == (unsigned)(gridDim.x - 1));
        if (isLast) __threadfence();
    }
    __syncthreads();
    if (!isLast) return;

    __shared__ float smf[32][8][15];
    {
        const int fb = tid >> 3, grp = tid & 7;
        float part[15];
#pragma unroll
        for (int k = 0; k < 15; k++) part[k] = 0.f;
#pragma unroll
        for (int q = 0; q < 4; q++) {
            int sc = grp * 4 + q;
#pragma unroll
            for (int k = 0; k < 7; k++) part[k] += g_part[fb][sc][k];
        }
#pragma unroll
        for (int q = 0; q < 6; q++) {
            int Wq = grp * 6 + q;
#pragma unroll
            for (int k = 0; k < 6; k++) part[7 + k] += (float)g_str[fb][Wq][k];
            part[13] += (float)g_med[fb][0][Wq];
            part[14] += (float)g_med[fb][1][Wq];
        }
#pragma unroll
        for (int k = 0; k < 15; k++) smf[fb][grp][k] = part[k];
    }
    __syncthreads();
    if (tid < 32) {
        const int bb = tid;
        float a[15];
#pragma unroll
        for (int k = 0; k < 15; k++) {
            float v = 0.f;
#pragma unroll
            for (int g2 = 0; g2 < 8; g2++) v += smf[bb][g2][k];
            a[k] = v;
        }
        const float Sp = a[0], Spg = a[1];
        const float pec = a[2], pmc = a[3], pjc = a[4];
        const float Np = a[5], Ng = a[6];
        const float gec = a[7], gmc = a[8], gjc = a[9];
        const float Ie = a[10], Im = a[11], Ij = a[12];
        const float medP = a[13] + Np;   // + d>=1 term for every on-pixel
        const float medG = a[14] + Ng;
        const float Sg = Ng;

        float dice = (2.0f * Spg + 1.0f) / (Sp + Sg + 1.0f);
        float eiou = (Ie + 1.0f) / (pec + gec - Ie + 1.0f);
        float miou = (Im + 1.0f) / (pmc + gmc - Im + 1.0f);
        float jiou = (Ij + 1.0f) / (pjc + gjc - Ij + 1.0f);
        float total3 = gec + gjc + gmc + 1.0f;
        float sloss = 1.0f - ((gec / total3) * eiou + (gjc / total3) * jiou
                              + (gmc / total3) * miou);
        float p2g = medP / (Np + 1.0f);
        float g2p = medG / (Ng + 1.0f);
        float med = ((p2g + g2p) * 0.5f) / 10.0f;

        float sd = dice, ss = sloss, sme = med;
#pragma unroll
        for (int off = 16; off > 0; off >>= 1) {
            sd  += __shfl_down_sync(0xFFFFFFFFu, sd, off);
            ss  += __shfl_down_sync(0xFFFFFFFFu, ss, off);
            sme += __shfl_down_sync(0xFFFFFFFFu, sme, off);
        }
        if (tid == 0) {
            float dice_loss = 1.0f - sd / 32.0f;
            float structural_loss = ss / 32.0f;
            float medial_loss = sme / 32.0f;
            float avg = (dice_loss + structural_loss + medial_loss) / 3.0f;
            out[0] = dice_loss / (dice_loss + 1.0f) * avg
                   + structural_loss / (structural_loss + 1.0f) * avg
                   + medial_loss / (medial_loss + 1.0f) * avg;
            g_ticket = 0u;  // reset for next graph replay
        }
    }
}

extern "C" void kernel_launch(void* const* d_in, const int* in_sizes, int n_in,
                              void* d_out, int out_size) {
    const float* pred = (const float*)d_in[0];
    const float* gt   = (const float*)d_in[1];
    float* out = (float*)d_out;

    k1_pixel<<<NB * 32, 256>>>(pred, gt);   // 1024 blocks: (batch, strip, 64-row chunk)
    k2_dilate<<<K2BLK, 256>>>(out);         // 384 blocks: one warp item per warp
}